// round 11
// baseline (speedup 1.0000x reference)
#include <cuda_runtime.h>
#include <math.h>

#define NB   2048
#define NC   9605
#define NL   20
#define TPB  256
#define MAXWL 2048

#define ALPHA   0.5f
#define ALPHA1  0.05f
#define ALPHA2  2.0f
#define ALPHA3  10.0f

__device__ int g_wl_cnt;
__device__ int g_wl_packed[MAXWL];   // (class_idx << 5) | group_id

// ---------------------------------------------------------------------------
// Fused prelude (single block): detect mask dtype, build whitelist list,
// zero the output accumulator.
// ---------------------------------------------------------------------------
__global__ __launch_bounds__(1024)
void prelude_kernel(const void* __restrict__ maskv, float* __restrict__ out) {
    const int tid = threadIdx.x;
    const unsigned char* mb = (const unsigned char*)maskv;

    // dtype detection: in an int32 0/1 buffer nonzero bytes sit only at
    // offset%4==0; a uint8 bool buffer has misaligned nonzero bytes a.s.
    int local = 0;
    for (int i = tid; i < NL * NC; i += 1024)
        if ((i & 3) != 0 && mb[i] != 0) local = 1;
    const int u8 = __syncthreads_or(local);

    if (tid == 0) { g_wl_cnt = 0; out[0] = 0.0f; }
    __syncthreads();

    for (int c = tid; c < NC; c += 1024) {
        int g = -1;
        if (u8) {
            #pragma unroll
            for (int l = 0; l < NL; l++)
                if (mb[(size_t)l * NC + c]) { g = l; break; }
        } else {
            const int* mi = (const int*)maskv;
            #pragma unroll
            for (int l = 0; l < NL; l++)
                if (mi[(size_t)l * NC + c] != 0) { g = l; break; }
        }
        if (g >= 0) {
            int pos = atomicAdd(&g_wl_cnt, 1);
            if (pos < MAXWL) g_wl_packed[pos] = (c << 5) | g;
        }
    }
}

// ---------------------------------------------------------------------------
// Helpers
// ---------------------------------------------------------------------------
__device__ __forceinline__ unsigned int fenc(float f) {
    unsigned int u = __float_as_uint(f);
    return (u & 0x80000000u) ? ~u : (u | 0x80000000u);
}
__device__ __forceinline__ float fdec(unsigned int u) {
    return (u & 0x80000000u) ? __uint_as_float(u ^ 0x80000000u)
                             : __uint_as_float(~u);
}
__device__ __forceinline__ float sigmoidf_(float v) {
    return 1.0f / (1.0f + expf(-v));
}
__device__ __forceinline__ float rank_loss(float x1, float x2) {
    float d = x2 - x1 + ALPHA1;
    float s = 1.0f / (1.0f + expf(-ALPHA3 * d));
    return (d > 0.0f) ? (ALPHA2 * s) : s;
}

#define TOP11_INSERT(t, v)                                   \
    if ((v) > t[10]) {                                       \
        t[10] = (v);                                         \
        _Pragma("unroll")                                    \
        for (int _j = 10; _j > 0; _j--) {                    \
            float _a = t[_j - 1], _b = t[_j];                \
            t[_j - 1] = fmaxf(_a, _b);                       \
            t[_j]     = fminf(_a, _b);                       \
        }                                                    \
    }

// ---------------------------------------------------------------------------
// One block per row. Accumulates the loss into out[0] via atomicAdd.
// ---------------------------------------------------------------------------
__global__ __launch_bounds__(TPB)
void row_loss_kernel(const float* __restrict__ x,
                     const int*   __restrict__ y,
                     const int*   __restrict__ yneg,
                     float*       __restrict__ out) {
    const int b   = blockIdx.x;
    const int tid = threadIdx.x;

    __shared__ unsigned int gmax_sh[NL];
    __shared__ int act_sh[NL];
    __shared__ int actn_sh[NL];
    __shared__ float tops[TPB * 11];

    if (tid < NL) {
        gmax_sh[tid] = fenc(-3.0e38f);
        act_sh[tid]  = 0;
        actn_sh[tid] = 0;
    }
    __syncthreads();

    const float* xr  = x    + (size_t)b * NC;
    const int*   yr  = y    + (size_t)b * NC;
    const int*   ynr = yneg + (size_t)b * NC;

    // Per-thread top-11, initialized to 0.0f. EXACT: the threshold is
    // sigmoid(max(x11, 0)), and merging the row with extra zeros yields
    // max(x11, 0) in slot 10. This kills the -inf warm-up insert storm and
    // all triggers from negative values (~50% of data).
    float t[11];
    #pragma unroll
    for (int i = 0; i < 11; i++) t[i] = 0.0f;

    // ---- Dense phase: float4 top-11 scan, unrolled x2 --------------------
    const int p    = (int)(((16u - ((unsigned)(size_t)xr & 15u)) & 15u) >> 2);
    const int nvec = (NC - p) >> 2;
    const int tail = p + (nvec << 2);

    for (int c = tid; c < p; c += TPB) {
        float v = __ldg(xr + c);
        TOP11_INSERT(t, v);
    }
    const float4* v4 = (const float4*)(xr + p);
    int i = tid;
    for (; i + TPB < nvec; i += 2 * TPB) {
        float4 q0 = __ldg(v4 + i);
        float4 q1 = __ldg(v4 + i + TPB);
        float m0 = fmaxf(fmaxf(q0.x, q0.y), fmaxf(q0.z, q0.w));
        float m1 = fmaxf(fmaxf(q1.x, q1.y), fmaxf(q1.z, q1.w));
        if (fmaxf(m0, m1) > t[10]) {               // rare: needs a positive
            TOP11_INSERT(t, q0.x); TOP11_INSERT(t, q0.y);
            TOP11_INSERT(t, q0.z); TOP11_INSERT(t, q0.w);
            TOP11_INSERT(t, q1.x); TOP11_INSERT(t, q1.y);
            TOP11_INSERT(t, q1.z); TOP11_INSERT(t, q1.w);
        }
    }
    if (i < nvec) {
        float4 q = __ldg(v4 + i);
        float m = fmaxf(fmaxf(q.x, q.y), fmaxf(q.z, q.w));
        if (m > t[10]) {
            TOP11_INSERT(t, q.x); TOP11_INSERT(t, q.y);
            TOP11_INSERT(t, q.z); TOP11_INSERT(t, q.w);
        }
    }
    for (int c = tail + tid; c < NC; c += TPB) {
        float v = __ldg(xr + c);
        TOP11_INSERT(t, v);
    }

    // ---- Whitelist phase: ~1000 compact gathers (x is L1/L2-hot) ---------
    const int cnt = g_wl_cnt;
    for (int w = tid; w < cnt; w += TPB) {
        int pk  = g_wl_packed[w];
        int c   = pk >> 5;
        int gid = pk & 31;
        float v = __ldg(xr + c);
        atomicMax(&gmax_sh[gid], fenc(v));
        if (__ldg(yr + c) != 0)  act_sh[gid]  = 1;  // idempotent
        if (__ldg(ynr + c) != 0) actn_sh[gid] = 1;
    }

    #pragma unroll
    for (int k = 0; k < 11; k++) tops[tid * 11 + k] = t[k];
    __syncthreads();

    // ---- Tree-merge sorted 11-lists --------------------------------------
    for (int s = TPB / 2; s >= 1; s >>= 1) {
        if (tid < s) {
            float* A  = &tops[tid * 11];
            float* Bp = &tops[(tid + s) * 11];
            float outm[11];
            int a = 0, bj = 0;
            #pragma unroll
            for (int k = 0; k < 11; k++) {
                float av = A[a], bv = Bp[bj];
                if (av >= bv) { outm[k] = av; a++; }
                else          { outm[k] = bv; bj++; }
            }
            #pragma unroll
            for (int k = 0; k < 11; k++) A[k] = outm[k];
        }
        __syncthreads();
    }

    // ---- Scalar epilogue --------------------------------------------------
    if (tid == 0) {
        float x11   = tops[10];                 // == max(true x11, 0)
        float thres = sigmoidf_(x11);

        float s_l[NL];
        int   g = -1;
        float union_max = 0.0f;
        #pragma unroll
        for (int l = 0; l < NL; l++) {
            s_l[l] = sigmoidf_(fdec(gmax_sh[l]));
            union_max = fmaxf(union_max, s_l[l]);
            if (g < 0 && act_sh[l]) g = l;
        }
        bool has_gt = (g >= 0);

        float incorrect_neg = 0.0f;
        #pragma unroll
        for (int l = 0; l < NL; l++)
            if (actn_sh[l]) incorrect_neg = fmaxf(incorrect_neg, s_l[l]);

        float loss;
        if (!has_gt) {
            loss = (1.0f - ALPHA) * rank_loss(thres, union_max)
                 + ALPHA          * rank_loss(thres, incorrect_neg);
        } else {
            float gt_max = s_l[g];
            float incorrect_max = 0.0f;
            #pragma unroll
            for (int l = 0; l < NL; l++)
                if (l != g) incorrect_max = fmaxf(incorrect_max, s_l[l]);

            loss = rank_loss(gt_max, thres);
            if (incorrect_max > 0.0f)
                loss += (1.0f - ALPHA) * rank_loss(thres, incorrect_max);
            if (incorrect_neg > 0.0f)
                loss += ALPHA * rank_loss(thres, incorrect_neg);
            else
                loss += ALPHA * rank_loss(thres, incorrect_max);
        }
        atomicAdd(out, loss);
    }
}

extern "C" void kernel_launch(void* const* d_in, const int* in_sizes, int n_in,
                              void* d_out, int out_size) {
    const float* x    = (const float*)d_in[0];
    const int*   y    = (const int*)d_in[1];
    const int*   yneg = (const int*)d_in[2];
    const void*  gmask = d_in[3];

    prelude_kernel<<<1, 1024>>>(gmask, (float*)d_out);
    row_loss_kernel<<<NB, TPB>>>(x, y, yneg, (float*)d_out);
}

// round 12
// speedup vs baseline: 2.3043x; 2.3043x over previous
#include <cuda_runtime.h>
#include <math.h>

#define NB    2048
#define NC    9605
#define NL    20
#define TPB   256
#define MAXWL 2048
#define CAP   1024          // candidate buffer capacity
#define THR   2.0f          // conservative prefilter; exact via fallback

#define ALPHA   0.5f
#define ALPHA1  0.05f
#define ALPHA2  2.0f
#define ALPHA3  10.0f

__device__ int g_mask_is_u8 = 0;   // set once (data property) -> deterministic
__device__ int g_wl_cnt;
__device__ int g_wl_packed[MAXWL]; // (class_idx << 5) | group_id

// ---------------------------------------------------------------------------
// Prelude A: vectorized dtype detect + zero init.
// int32 0/1 buffer: bytes 1..3 of every word are zero. uint8 bool buffer:
// ~1000 trues hit misaligned byte offsets almost surely.
// ---------------------------------------------------------------------------
__global__ void detect_kernel(const unsigned char* __restrict__ mask,
                              float* __restrict__ out) {
    const int i = blockIdx.x * blockDim.x + threadIdx.x;
    if (i == 0) { g_wl_cnt = 0; out[0] = 0.0f; }
    const int nvec = (NL * NC) / 16;           // 12006
    if (i < nvec) {
        uint4 w = ((const uint4*)mask)[i];
        unsigned int chk = (w.x & 0xFFFFFF00u) | (w.y & 0xFFFFFF00u)
                         | (w.z & 0xFFFFFF00u) | (w.w & 0xFFFFFF00u);
        if (chk) atomicOr(&g_mask_is_u8, 1);
    }
    if (i == 0) {                              // 4-byte tail word
        unsigned int wt = ((const unsigned int*)mask)[(NL * NC) / 4 - 1];
        if (wt & 0xFFFFFF00u) atomicOr(&g_mask_is_u8, 1);
    }
}

// ---------------------------------------------------------------------------
// Prelude B: build compact whitelist list.
// ---------------------------------------------------------------------------
__global__ void build_wl_kernel(const void* __restrict__ maskv) {
    int c = blockIdx.x * blockDim.x + threadIdx.x;
    if (c >= NC) return;
    const int u8 = g_mask_is_u8;
    int g = -1;
    if (u8) {
        const unsigned char* m = (const unsigned char*)maskv;
        #pragma unroll
        for (int l = 0; l < NL; l++)
            if (m[(size_t)l * NC + c]) { g = l; break; }
    } else {
        const int* m = (const int*)maskv;
        #pragma unroll
        for (int l = 0; l < NL; l++)
            if (m[(size_t)l * NC + c] != 0) { g = l; break; }
    }
    if (g >= 0) {
        int pos = atomicAdd(&g_wl_cnt, 1);
        if (pos < MAXWL) g_wl_packed[pos] = (c << 5) | g;
    }
}

// ---------------------------------------------------------------------------
// Helpers
// ---------------------------------------------------------------------------
__device__ __forceinline__ unsigned int fenc(float f) {
    unsigned int u = __float_as_uint(f);
    return (u & 0x80000000u) ? ~u : (u | 0x80000000u);
}
__device__ __forceinline__ float fdec(unsigned int u) {
    return (u & 0x80000000u) ? __uint_as_float(u ^ 0x80000000u)
                             : __uint_as_float(~u);
}
__device__ __forceinline__ float sigmoidf_(float v) {
    return 1.0f / (1.0f + expf(-v));
}
__device__ __forceinline__ float rank_loss(float x1, float x2) {
    float d = x2 - x1 + ALPHA1;
    float s = 1.0f / (1.0f + expf(-ALPHA3 * d));
    return (d > 0.0f) ? (ALPHA2 * s) : s;
}

#define TOP11_INSERT(t, v)                                   \
    if ((v) > t[10]) {                                       \
        t[10] = (v);                                         \
        _Pragma("unroll")                                    \
        for (int _j = 10; _j > 0; _j--) {                    \
            float _a = t[_j - 1], _b = t[_j];                \
            t[_j - 1] = fmaxf(_a, _b);                       \
            t[_j]     = fminf(_a, _b);                       \
        }                                                    \
    }

// ---------------------------------------------------------------------------
// One block per row.
// ---------------------------------------------------------------------------
__global__ __launch_bounds__(TPB)
void row_loss_kernel(const float* __restrict__ x,
                     const int*   __restrict__ y,
                     const int*   __restrict__ yneg,
                     float*       __restrict__ out) {
    const int b   = blockIdx.x;
    const int tid = threadIdx.x;

    __shared__ unsigned int gmax_sh[NL];
    __shared__ int   act_sh[NL];
    __shared__ int   actn_sh[NL];
    __shared__ int   ncand_sh;
    __shared__ float cand_sh[CAP];
    __shared__ float tops[32 * 11];
    __shared__ float x11_sh;

    if (tid < NL) {
        gmax_sh[tid] = fenc(-3.0e38f);
        act_sh[tid]  = 0;
        actn_sh[tid] = 0;
    }
    if (tid == 0) ncand_sh = 0;
    __syncthreads();

    const float* xr  = x    + (size_t)b * NC;
    const int*   yr  = y    + (size_t)b * NC;
    const int*   ynr = yneg + (size_t)b * NC;

    // ---- Dense phase: stream the row, push candidates > THR --------------
    #define PUSH_CAND(v)                                     \
        if ((v) > THR) {                                     \
            int _p = atomicAdd(&ncand_sh, 1);                \
            if (_p < CAP) cand_sh[_p] = (v);                 \
        }

    const int p    = (int)(((16u - ((unsigned)(size_t)xr & 15u)) & 15u) >> 2);
    const int nvec = (NC - p) >> 2;
    const int tail = p + (nvec << 2);

    for (int c = tid; c < p; c += TPB) {
        float v = __ldg(xr + c);
        PUSH_CAND(v);
    }
    const float4* v4 = (const float4*)(xr + p);
    int i = tid;
    for (; i + TPB < nvec; i += 2 * TPB) {
        float4 q0 = __ldg(v4 + i);
        float4 q1 = __ldg(v4 + i + TPB);
        float m0 = fmaxf(fmaxf(q0.x, q0.y), fmaxf(q0.z, q0.w));
        float m1 = fmaxf(fmaxf(q1.x, q1.y), fmaxf(q1.z, q1.w));
        if (fmaxf(m0, m1) > THR) {
            PUSH_CAND(q0.x); PUSH_CAND(q0.y); PUSH_CAND(q0.z); PUSH_CAND(q0.w);
            PUSH_CAND(q1.x); PUSH_CAND(q1.y); PUSH_CAND(q1.z); PUSH_CAND(q1.w);
        }
    }
    if (i < nvec) {
        float4 q = __ldg(v4 + i);
        float m = fmaxf(fmaxf(q.x, q.y), fmaxf(q.z, q.w));
        if (m > THR) {
            PUSH_CAND(q.x); PUSH_CAND(q.y); PUSH_CAND(q.z); PUSH_CAND(q.w);
        }
    }
    for (int c = tail + tid; c < NC; c += TPB) {
        float v = __ldg(xr + c);
        PUSH_CAND(v);
    }
    __syncthreads();

    if (tid < 32) {
        // ---- Warp 0: top-11 selection over candidates --------------------
        const int n = ncand_sh;
        float t[11];
        #pragma unroll
        for (int k = 0; k < 11; k++) t[k] = 0.0f;   // thres uses max(x11,0)

        if (n >= 11 && n <= CAP) {
            for (int c = tid; c < n; c += 32) {
                float v = cand_sh[c];
                TOP11_INSERT(t, v);
            }
        } else {
            // Fallback (exact for any input; never taken on this data).
            for (int c = tid; c < NC; c += 32) {
                float v = __ldg(xr + c);
                TOP11_INSERT(t, v);
            }
        }
        #pragma unroll
        for (int k = 0; k < 11; k++) tops[tid * 11 + k] = t[k];
        __syncwarp();

        for (int s = 16; s >= 1; s >>= 1) {
            if (tid < s) {
                float* A  = &tops[tid * 11];
                float* Bp = &tops[(tid + s) * 11];
                float outm[11];
                int a = 0, bj = 0;
                #pragma unroll
                for (int k = 0; k < 11; k++) {
                    float av = A[a], bv = Bp[bj];
                    if (av >= bv) { outm[k] = av; a++; }
                    else          { outm[k] = bv; bj++; }
                }
                #pragma unroll
                for (int k = 0; k < 11; k++) A[k] = outm[k];
            }
            __syncwarp();
        }
        if (tid == 0) x11_sh = tops[10];            // == max(x11, 0)
    } else {
        // ---- Warps 1-7: whitelist gathers (concurrent with selection) ----
        const int cnt = g_wl_cnt;
        for (int w = tid - 32; w < cnt; w += TPB - 32) {
            int pk  = g_wl_packed[w];
            int c   = pk >> 5;
            int gid = pk & 31;
            float v = __ldg(xr + c);                // L1-hot from dense scan
            atomicMax(&gmax_sh[gid], fenc(v));
            if (__ldg(yr + c) != 0)  act_sh[gid]  = 1;  // idempotent
            if (__ldg(ynr + c) != 0) actn_sh[gid] = 1;
        }
    }
    __syncthreads();

    // ---- Scalar epilogue --------------------------------------------------
    if (tid == 0) {
        float thres = sigmoidf_(x11_sh);

        float s_l[NL];
        int   g = -1;
        float union_max = 0.0f;
        #pragma unroll
        for (int l = 0; l < NL; l++) {
            s_l[l] = sigmoidf_(fdec(gmax_sh[l]));
            union_max = fmaxf(union_max, s_l[l]);
            if (g < 0 && act_sh[l]) g = l;
        }
        bool has_gt = (g >= 0);

        float incorrect_neg = 0.0f;
        #pragma unroll
        for (int l = 0; l < NL; l++)
            if (actn_sh[l]) incorrect_neg = fmaxf(incorrect_neg, s_l[l]);

        float loss;
        if (!has_gt) {
            loss = (1.0f - ALPHA) * rank_loss(thres, union_max)
                 + ALPHA          * rank_loss(thres, incorrect_neg);
        } else {
            float gt_max = s_l[g];
            float incorrect_max = 0.0f;
            #pragma unroll
            for (int l = 0; l < NL; l++)
                if (l != g) incorrect_max = fmaxf(incorrect_max, s_l[l]);

            loss = rank_loss(gt_max, thres);
            if (incorrect_max > 0.0f)
                loss += (1.0f - ALPHA) * rank_loss(thres, incorrect_max);
            if (incorrect_neg > 0.0f)
                loss += ALPHA * rank_loss(thres, incorrect_neg);
            else
                loss += ALPHA * rank_loss(thres, incorrect_max);
        }
        atomicAdd(out, loss);
    }
}

extern "C" void kernel_launch(void* const* d_in, const int* in_sizes, int n_in,
                              void* d_out, int out_size) {
    const float* x    = (const float*)d_in[0];
    const int*   y    = (const int*)d_in[1];
    const int*   yneg = (const int*)d_in[2];
    const void*  gmask = d_in[3];

    detect_kernel<<<(NL * NC / 16 + 255) / 256, 256>>>(
        (const unsigned char*)gmask, (float*)d_out);
    build_wl_kernel<<<(NC + 255) / 256, 256>>>(gmask);
    row_loss_kernel<<<NB, TPB>>>(x, y, yneg, (float*)d_out);
}